// round 6
// baseline (speedup 1.0000x reference)
#include <cuda_runtime.h>

// MultiLayerGRU fused: 3 stacked GRU layers, T=1024, B=4096, I=5, H0=15, H1=10, H2=2.
// One warp per TWO batch elements; 2048 warps total so each SMSP carries ~3.5
// warps (the R3-R5 analysis showed 2 warps/SMSP left issue at 53%).
// Weights are packed as consecutive-k pairs (w_k, w_{k+1}) for fma.rn.f32x2
// (dot-product style, horizontal add at the end) -> 90 weight regs instead of
// 170 duplicated ones, enabling 7 CTAs x 64 thr per SM.
// Lane roles:
//   lanes  0..14 : layer-0 units
//   lanes 15..24 : layer-1 units
//   lanes 25..26 : layer-2 units (write the output)
//   lanes 27..31 : x-feature loaders (prefetch x[t] into registers)
// Wavefront over layers: iteration s computes h0(s), h1(s-1), h2(s-2).
// Unified slot space t = 0..25 (13 pairs); operand at slot t is published by
// lane (base+t) mod 32, base in {27,0,15}. r/z span slots 0..25, ni slots
// 0..15 (pairs 0..7), nh slots 4..25 (pairs 2..12); unused slots have w=0.

#define T_STEPS 1024
#define BATCH   4096
#define IN_DIM  5

using u64 = unsigned long long;

__device__ __forceinline__ u64 pack2(float a, float b) {
    u64 r;
    asm("mov.b64 %0, {%1, %2};" : "=l"(r) : "f"(a), "f"(b));
    return r;
}
__device__ __forceinline__ void unpack2(u64 p, float& a, float& b) {
    asm("mov.b64 {%0, %1}, %2;" : "=f"(a), "=f"(b) : "l"(p));
}
__device__ __forceinline__ u64 fma2(u64 a, u64 b, u64 c) {
    u64 d;
    asm("fma.rn.f32x2 %0, %1, %2, %3;" : "=l"(d) : "l"(a), "l"(b), "l"(c));
    return d;
}
__device__ __forceinline__ float hadd2(u64 p) {
    float a, b;
    unpack2(p, a, b);
    return a + b;
}

__device__ __forceinline__ float fsig(float a) {
    return __fdividef(1.0f, 1.0f + __expf(-a));
}
__device__ __forceinline__ float ftanh_(float v) {
    return 1.0f - 2.0f * __fdividef(1.0f, 1.0f + __expf(2.0f * v));
}

__global__ __launch_bounds__(64, 7)
void gru3_fused_kernel(
    const float* __restrict__ x,
    const float* __restrict__ w_ih0, const float* __restrict__ w_hh0,
    const float* __restrict__ b_ih0, const float* __restrict__ b_hh0,
    const float* __restrict__ w_ih1, const float* __restrict__ w_hh1,
    const float* __restrict__ b_ih1, const float* __restrict__ b_hh1,
    const float* __restrict__ w_ih2, const float* __restrict__ w_hh2,
    const float* __restrict__ b_ih2, const float* __restrict__ b_hh2,
    float* __restrict__ out)
{
    // ---- stage all weights into shared once ----
    __shared__ float sw[1884];
    {
        int t = threadIdx.x;
        for (int i = t; i < 225; i += 64) sw[i]        = w_ih0[i];
        for (int i = t; i < 675; i += 64) sw[225 + i]  = w_hh0[i];
        for (int i = t; i <  45; i += 64) sw[900 + i]  = b_ih0[i];
        for (int i = t; i <  45; i += 64) sw[945 + i]  = b_hh0[i];
        for (int i = t; i < 450; i += 64) sw[990 + i]  = w_ih1[i];
        for (int i = t; i < 300; i += 64) sw[1440 + i] = w_hh1[i];
        for (int i = t; i <  30; i += 64) sw[1740 + i] = b_ih1[i];
        for (int i = t; i <  30; i += 64) sw[1770 + i] = b_hh1[i];
        for (int i = t; i <  60; i += 64) sw[1800 + i] = w_ih2[i];
        for (int i = t; i <  12; i += 64) sw[1860 + i] = w_hh2[i];
        for (int i = t; i <   6; i += 64) sw[1872 + i] = b_ih2[i];
        for (int i = t; i <   6; i += 64) sw[1878 + i] = b_hh2[i];
    }
    __syncthreads();
    const float* s_wih0 = sw;
    const float* s_whh0 = sw + 225;
    const float* s_bih0 = sw + 900;
    const float* s_bhh0 = sw + 945;
    const float* s_wih1 = sw + 990;
    const float* s_whh1 = sw + 1440;
    const float* s_bih1 = sw + 1740;
    const float* s_bhh1 = sw + 1770;
    const float* s_wih2 = sw + 1800;
    const float* s_whh2 = sw + 1860;
    const float* s_bih2 = sw + 1872;
    const float* s_bhh2 = sw + 1878;

    const int lane = threadIdx.x & 31;
    const int gw   = blockIdx.x * 2 + (threadIdx.x >> 5);
    const int b0   = gw * 2;             // batches b0, b0+1

    // ---- per-lane scalar weights over unified slots (then pair-packed) ----
    float wrS[26], wzS[26], wniS[16], wnhS[22];   // wnhS[i] = slot 4+i
#pragma unroll
    for (int t = 0; t < 26; t++) { wrS[t] = 0.f; wzS[t] = 0.f; }
#pragma unroll
    for (int t = 0; t < 16; t++) wniS[t] = 0.f;
#pragma unroll
    for (int t = 0; t < 22; t++) wnhS[t] = 0.f;
    float br = 0.f, bz = 0.f, bni = 0.f, bnh = 0.f;

    if (lane < 15) {                 // L0: slots 0..4 = x, 5..19 = h0
        const int u = lane;
#pragma unroll
        for (int k = 0; k < 5; k++) {
            wrS[k]  = s_wih0[u * 5 + k];
            wzS[k]  = s_wih0[(15 + u) * 5 + k];
            wniS[k] = s_wih0[(30 + u) * 5 + k];
        }
#pragma unroll
        for (int j = 0; j < 15; j++) {
            wrS[5 + j]      = s_whh0[u * 15 + j];
            wzS[5 + j]      = s_whh0[(15 + u) * 15 + j];
            wnhS[(5 + j)-4] = s_whh0[(30 + u) * 15 + j];   // slots 5..19
        }
        br  = s_bih0[u] + s_bhh0[u];
        bz  = s_bih0[15 + u] + s_bhh0[15 + u];
        bni = s_bih0[30 + u];
        bnh = s_bhh0[30 + u];
    } else if (lane < 25) {          // L1: slots 0..14 = o0, 15..24 = h1
        const int u = lane - 15;
#pragma unroll
        for (int k = 0; k < 15; k++) {
            wrS[k]  = s_wih1[u * 15 + k];
            wzS[k]  = s_wih1[(10 + u) * 15 + k];
            wniS[k] = s_wih1[(20 + u) * 15 + k];
        }
#pragma unroll
        for (int j = 0; j < 10; j++) {
            wrS[15 + j]       = s_whh1[u * 10 + j];
            wzS[15 + j]       = s_whh1[(10 + u) * 10 + j];
            wnhS[(15 + j)-4]  = s_whh1[(20 + u) * 10 + j];  // slots 15..24
        }
        br  = s_bih1[u] + s_bhh1[u];
        bz  = s_bih1[10 + u] + s_bhh1[10 + u];
        bni = s_bih1[20 + u];
        bnh = s_bhh1[20 + u];
    } else if (lane < 27) {          // L2: slots 0..9 = o1, 10..11 = h2
        const int u = lane - 25;
#pragma unroll
        for (int k = 0; k < 10; k++) {
            wrS[k]  = s_wih2[u * 10 + k];
            wzS[k]  = s_wih2[(2 + u) * 10 + k];
            wniS[k] = s_wih2[(4 + u) * 10 + k];
        }
#pragma unroll
        for (int j = 0; j < 2; j++) {
            wrS[10 + j]      = s_whh2[u * 2 + j];
            wzS[10 + j]      = s_whh2[(2 + u) * 2 + j];
            wnhS[(10 + j)-4] = s_whh2[(4 + u) * 2 + j];     // slots 10..11
        }
        br  = s_bih2[u] + s_bhh2[u];
        bz  = s_bih2[2 + u] + s_bhh2[2 + u];
        bni = s_bih2[4 + u];
        bnh = s_bhh2[4 + u];
    }

    // pair-packed weights: (w_{2k}, w_{2k+1}) — no duplication
    u64 wr2[13], wz2[13], wni2[8], wnh2[11];
#pragma unroll
    for (int k = 0; k < 13; k++) {
        wr2[k] = pack2(wrS[2 * k], wrS[2 * k + 1]);
        wz2[k] = pack2(wzS[2 * k], wzS[2 * k + 1]);
    }
#pragma unroll
    for (int k = 0; k < 8; k++)  wni2[k] = pack2(wniS[2 * k], wniS[2 * k + 1]);   // slots 0..15
#pragma unroll
    for (int k = 0; k < 11; k++) wnh2[k] = pack2(wnhS[2 * k], wnhS[2 * k + 1]);   // slots 4..25
    // bias folded into packed accumulator init (lo half)
    const u64 br2  = pack2(br, 0.f);
    const u64 bz2  = pack2(bz, 0.f);
    const u64 bni2 = pack2(bni, 0.f);
    const u64 bnh2 = pack2(bnh, 0.f);

    // shfl base per lane class: slot t is published by lane base+t (mod 32)
    const int base = (lane < 15) ? 27 : (lane < 25) ? 0 : 15;

    const bool isLoader = (lane >= 27);
    const bool isOut    = (lane == 25) || (lane == 26);
    // wavefront delay per lane; loader lanes never commit
    const int d = (lane < 15) ? 0 : (lane < 25) ? 1 : (lane < 27) ? 2 : 0x40000000;

    const int feat = isLoader ? (lane - 27) : 0;
    const float* xp = x + (size_t)b0 * IN_DIM + feat;
    const int u2 = (lane >= 25) ? (lane - 25) : 0;
    float* op = out + (size_t)b0 * 2 + u2;

    float hA = 0.f, hB = 0.f;         // hidden state, 2 batches
    float xnA = 0.f, xnB = 0.f;       // prefetched x(t+1)
    float shA = 0.f, shB = 0.f;       // published operands
    if (isLoader) {
        shA = xp[0];                              // x(0)
        shB = xp[IN_DIM];
        xnA = xp[BATCH * IN_DIM];                 // x(1)
        xnB = xp[BATCH * IN_DIM + IN_DIM];
    }

    for (int s = 0; s < T_STEPS + 2; ++s) {
        u64 arA = br2, azA = bz2, aniA = bni2, anhA = bnh2;
        u64 arB = br2, azB = bz2, aniB = bni2, anhB = bnh2;
#pragma unroll
        for (int k = 0; k < 13; k++) {
            float a0 = __shfl_sync(0xffffffffu, shA, base + 2 * k);      // wraps mod 32
            float a1 = __shfl_sync(0xffffffffu, shA, base + 2 * k + 1);
            float b0f = __shfl_sync(0xffffffffu, shB, base + 2 * k);
            float b1f = __shfl_sync(0xffffffffu, shB, base + 2 * k + 1);
            u64 vA = pack2(a0, a1);
            u64 vB = pack2(b0f, b1f);
            arA = fma2(wr2[k], vA, arA);
            arB = fma2(wr2[k], vB, arB);
            azA = fma2(wz2[k], vA, azA);
            azB = fma2(wz2[k], vB, azB);
            if (k < 8)  { aniA = fma2(wni2[k], vA, aniA); aniB = fma2(wni2[k], vB, aniB); }
            if (k >= 2) { anhA = fma2(wnh2[k - 2], vA, anhA); anhB = fma2(wnh2[k - 2], vB, anhB); }
        }

        float ar_A = hadd2(arA), ar_B = hadd2(arB);
        float az_A = hadd2(azA), az_B = hadd2(azB);
        float ani_A = hadd2(aniA), ani_B = hadd2(aniB);
        float anh_A = hadd2(anhA), anh_B = hadd2(anhB);

        float rA = fsig(ar_A), rB = fsig(ar_B);
        float zA = fsig(az_A), zB = fsig(az_B);
        float nA = ftanh_(fmaf(rA, anh_A, ani_A));
        float nB = ftanh_(fmaf(rB, anh_B, ani_B));
        float hnA = fmaf(zA, hA - nA, nA);        // (1-z)*n + z*h
        float hnB = fmaf(zB, hB - nB, nB);

        bool valid = (s >= d) && (s < T_STEPS + d);
        if (valid) { hA = hnA; hB = hnB; }
        if (valid && isOut) {
            size_t o = (size_t)(s - 2) * (BATCH * 2);
            op[o] = hnA;
            op[o + 2] = hnB;
        }

        if (isLoader) {
            shA = xnA;                            // becomes x(s+1)
            shB = xnB;
            int t2 = s + 2;
            bool inb = (t2 < T_STEPS);
            size_t xo = (size_t)t2 * (BATCH * IN_DIM);
            xnA = inb ? xp[xo] : 0.f;
            xnB = inb ? xp[xo + IN_DIM] : 0.f;
        } else {
            shA = hA;
            shB = hB;
        }
    }
}

extern "C" void kernel_launch(void* const* d_in, const int* in_sizes, int n_in,
                              void* d_out, int out_size)
{
    (void)in_sizes; (void)n_in; (void)out_size;
    const float* x     = (const float*)d_in[0];
    const float* w_ih0 = (const float*)d_in[1];
    const float* w_hh0 = (const float*)d_in[2];
    const float* b_ih0 = (const float*)d_in[3];
    const float* b_hh0 = (const float*)d_in[4];
    const float* w_ih1 = (const float*)d_in[5];
    const float* w_hh1 = (const float*)d_in[6];
    const float* b_ih1 = (const float*)d_in[7];
    const float* b_hh1 = (const float*)d_in[8];
    const float* w_ih2 = (const float*)d_in[9];
    const float* w_hh2 = (const float*)d_in[10];
    const float* b_ih2 = (const float*)d_in[11];
    const float* b_hh2 = (const float*)d_in[12];

    // one warp per 2 batch elements: 2048 warps = 1024 blocks x 64 threads
    gru3_fused_kernel<<<BATCH / 4, 64>>>(
        x, w_ih0, w_hh0, b_ih0, b_hh0,
        w_ih1, w_hh1, b_ih1, b_hh1,
        w_ih2, w_hh2, b_ih2, b_hh2,
        (float*)d_out);
}